// round 12
// baseline (speedup 1.0000x reference)
#include <cuda_runtime.h>
#include <cuda_bf16.h>
#include <cstdint>

#define NPTS   64
#define NANGS  2016
#define NCOLS  300000
#define NSEG   4
#define LSEG   (NANGS / NSEG)   // 504

typedef unsigned int u32;

__device__ float g_R[NPTS * NPTS];   // final R (only cross-kernel buffer)

__device__ __forceinline__ u32 smem_u32(const void* p) {
    u32 a;
    asm("{ .reg .u64 t; cvta.to.shared.u64 t, %1; cvt.u32.u64 %0, t; }"
        : "=r"(a) : "l"(p));
    return a;
}

// ---------------------------------------------------------------------------
// Fused build kernel: ONE block, 256 threads, 80 KB dynamic smem.
//   Phase 1: 4 segments x 64 columns; thread (s,j) applies rotations
//            [s*504,(s+1)*504) to column j with a 4-deep manual prefetch
//            pipeline (LDS issued 4 iters ahead of the aliasing STS).
//   Phase 2: 3 sequential 64x64x64 fp32 products (ping-pong in smem);
//            final product applies mus and writes g_R.
// Smem layout (floats): S0..S3 at s*4096 (64 KB), SCRATCH at 16384 (16 KB;
// doubles as the (cos,sin) table during phase 1).
// ---------------------------------------------------------------------------
extern __shared__ float sm_build[];

__device__ __forceinline__ void product64(
    const float* __restrict__ A, const float* __restrict__ B,
    float* __restrict__ Cs, float* __restrict__ gout,
    const float* __restrict__ mus, int tid)
{
    const int jc = (tid & 15) * 4;    // 4 consecutive output columns
    const int r0 = (tid >> 4) * 4;    // 4 consecutive output rows

    float acc[4][4];
#pragma unroll
    for (int i = 0; i < 4; i++)
#pragma unroll
        for (int c = 0; c < 4; c++) acc[i][c] = 0.0f;

#pragma unroll 4
    for (int k = 0; k < NPTS; k += 4) {
        float4 a[4], b[4];
#pragma unroll
        for (int i = 0; i < 4; i++)
            a[i] = *reinterpret_cast<const float4*>(&A[(r0 + i) * NPTS + k]);
#pragma unroll
        for (int kk = 0; kk < 4; kk++)
            b[kk] = *reinterpret_cast<const float4*>(&B[(k + kk) * NPTS + jc]);
#pragma unroll
        for (int i = 0; i < 4; i++) {
            acc[i][0] = fmaf(a[i].x, b[0].x, acc[i][0]);
            acc[i][1] = fmaf(a[i].x, b[0].y, acc[i][1]);
            acc[i][2] = fmaf(a[i].x, b[0].z, acc[i][2]);
            acc[i][3] = fmaf(a[i].x, b[0].w, acc[i][3]);
            acc[i][0] = fmaf(a[i].y, b[1].x, acc[i][0]);
            acc[i][1] = fmaf(a[i].y, b[1].y, acc[i][1]);
            acc[i][2] = fmaf(a[i].y, b[1].z, acc[i][2]);
            acc[i][3] = fmaf(a[i].y, b[1].w, acc[i][3]);
            acc[i][0] = fmaf(a[i].z, b[2].x, acc[i][0]);
            acc[i][1] = fmaf(a[i].z, b[2].y, acc[i][1]);
            acc[i][2] = fmaf(a[i].z, b[2].z, acc[i][2]);
            acc[i][3] = fmaf(a[i].z, b[2].w, acc[i][3]);
            acc[i][0] = fmaf(a[i].w, b[3].x, acc[i][0]);
            acc[i][1] = fmaf(a[i].w, b[3].y, acc[i][1]);
            acc[i][2] = fmaf(a[i].w, b[3].z, acc[i][2]);
            acc[i][3] = fmaf(a[i].w, b[3].w, acc[i][3]);
        }
    }

    if (gout) {
#pragma unroll
        for (int i = 0; i < 4; i++) {
            const float m = mus[r0 + i];
            float4 v = make_float4(m * acc[i][0], m * acc[i][1],
                                   m * acc[i][2], m * acc[i][3]);
            *reinterpret_cast<float4*>(&gout[(r0 + i) * NPTS + jc]) = v;
        }
    } else {
#pragma unroll
        for (int i = 0; i < 4; i++) {
            float4 v = make_float4(acc[i][0], acc[i][1], acc[i][2], acc[i][3]);
            *reinterpret_cast<float4*>(&Cs[(r0 + i) * NPTS + jc]) = v;
        }
    }
}

__global__ void __launch_bounds__(256, 1)
build_all_kernel(const float* __restrict__ angles, const float* __restrict__ mus) {
    float*  S       = sm_build;                       // 4 x 4096 floats
    float*  SCRATCH = sm_build + NSEG * NPTS * NPTS;  // 4096 floats
    float2* cs      = reinterpret_cast<float2*>(SCRATCH);  // 2016 float2 (fits)

    const int tid = threadIdx.x;
    const int s   = tid >> 6;     // segment 0..3
    const int j   = tid & 63;     // column

    // (cos,sin) table + identity init
    for (int i = tid; i < NANGS; i += 256) {
        float sv, cv;
        __sincosf(angles[i], &sv, &cv);
        cs[i] = make_float2(cv, sv);
    }
    for (int idx = tid; idx < NSEG * NPTS * NPTS; idx += 256) {
        const int e = idx & 4095;
        S[idx] = ((e >> 6) == (e & 63)) ? 1.0f : 0.0f;
    }
    __syncthreads();

    // ---- Phase 1: segment s, column j, 4-deep pipelined rotation chain ----
    {
        float* Sl = S + s * (NPTS * NPTS);
        const float2* csg = cs;            // global chain indexing
        const int i0 = s * LSEG;
        const int i1 = i0 + LSEG;

#pragma unroll 1
        for (int t = 0; t < NPTS - 1; t++) {
            const int gs   = t * (2 * NPTS - 1 - t) / 2;
            const int glen = NPTS - 1 - t;
            if (gs >= i1) break;
            if (gs + glen <= i0) continue;
            int lo = i0 - gs; if (lo < 0) lo = 0;
            int hi = i1 - gs; if (hi > glen) hi = glen;
            const int blen  = hi - lo;
            const int bbase = t + 1 + lo;
            const int ci    = gs + lo;

            float rt = Sl[t * NPTS + j];

            // preload ring (reads may run past blen / row 63 into the next
            // smem region — allocated, values unused)
            float  rb[4];
            float2 pp[4];
#pragma unroll
            for (int q = 0; q < 4; q++) {
                rb[q] = Sl[(bbase + q) * NPTS + j];
                pp[q] = csg[ci + q];
            }

            int ii = 0;
#pragma unroll 1
            for (; ii + 4 <= blen; ii += 4) {
#pragma unroll
                for (int q = 0; q < 4; q++) {
                    const float  rbv = rb[q];
                    const float2 p   = pp[q];
                    const int    nx  = ii + q + 4;
                    rb[q] = Sl[(bbase + nx) * NPTS + j];   // prefetch (before STS!)
                    pp[q] = csg[ci + nx];
                    Sl[(bbase + ii + q) * NPTS + j] = fmaf(p.y, rt, p.x * rbv);
                    rt = fmaf(p.x, rt, -(p.y * rbv));
                }
            }
            // tail (<4 iters, slots q = 0..blen-ii-1)
#pragma unroll
            for (int q = 0; q < 4; q++) {
                if (ii + q < blen) {
                    const float  rbv = rb[q];
                    const float2 p   = pp[q];
                    Sl[(bbase + ii + q) * NPTS + j] = fmaf(p.y, rt, p.x * rbv);
                    rt = fmaf(p.x, rt, -(p.y * rbv));
                }
            }
            Sl[t * NPTS + j] = rt;
        }
    }
    __syncthreads();   // cs region dead from here; SCRATCH reusable

    // ---- Phase 2: R = diag(mus) * S3 @ S2 @ S1 @ S0 (ping-pong) ----
    // step1: SCRATCH = S1 @ S0
    product64(S + 1 * 4096, S + 0 * 4096, SCRATCH, nullptr, nullptr, tid);
    __syncthreads();
    // step2: S0 = S2 @ SCRATCH
    product64(S + 2 * 4096, SCRATCH, S + 0 * 4096, nullptr, nullptr, tid);
    __syncthreads();
    // step3: g_R = mus * (S3 @ S0)
    product64(S + 3 * 4096, S + 0 * 4096, nullptr, g_R, mus, tid);
}

// ---------------------------------------------------------------------------
// GEMM: Y = R @ X via bf16 split-precision HMMA (3-term), proven R5 form:
//   Y ~= Rhi@Xhi + Rhi@Xlo + Rlo@Xhi   (fp32 accumulate)
// Warp tile 64x16, ldmatrix.x4 A-frags, 2-deep X prefetch, 3 blocks/SM.
// ---------------------------------------------------------------------------
#define LDR 36

#define CVT_PACK(d, x1, x0) \
    asm("cvt.rn.bf16x2.f32 %0, %1, %2;" : "=r"(d) : "f"(x1), "f"(x0))

#define LDMX4(R0, R1, R2, R3, ADDR)                                            \
    asm volatile("ldmatrix.sync.aligned.m8n8.x4.shared.b16 {%0,%1,%2,%3}, [%4];" \
                 : "=r"(R0), "=r"(R1), "=r"(R2), "=r"(R3) : "r"(ADDR))

#define MMA_BF16(ACC, A0, A1, A2, A3, B0, B1)                                  \
    asm volatile(                                                              \
        "mma.sync.aligned.m16n8k16.row.col.f32.bf16.bf16.f32 "                 \
        "{%0,%1,%2,%3},{%4,%5,%6,%7},{%8,%9},{%0,%1,%2,%3};"                   \
        : "+f"(ACC[0]), "+f"(ACC[1]), "+f"(ACC[2]), "+f"(ACC[3])               \
        : "r"(A0), "r"(A1), "r"(A2), "r"(A3), "r"(B0), "r"(B1))

__global__ void __launch_bounds__(256, 3)
gemm_hmma_kernel(const float* __restrict__ X, float* __restrict__ Y) {
    __shared__ u32 RhiS[NPTS * LDR];
    __shared__ u32 RloS[NPTS * LDR];

    for (int idx = threadIdx.x; idx < NPTS * 32; idx += 256) {
        const int row = idx >> 5, kp = idx & 31;
        const float x0 = g_R[row * NPTS + 2 * kp];
        const float x1 = g_R[row * NPTS + 2 * kp + 1];
        u32 hh; CVT_PACK(hh, x1, x0);
        const float h0 = __uint_as_float(hh << 16);
        const float h1 = __uint_as_float(hh & 0xFFFF0000u);
        u32 ll; CVT_PACK(ll, x1 - h1, x0 - h0);
        RhiS[row * LDR + kp] = hh;
        RloS[row * LDR + kp] = ll;
    }
    __syncthreads();

    const int warp = threadIdx.x >> 5;
    const int lane = threadIdx.x & 31;
    const int g = lane >> 2;
    const int t = lane & 3;

    const long n0 = (long)blockIdx.x * 128 + warp * 16;
    if (n0 + 16 > NCOLS) return;

    const int r8   = lane & 7;
    const int selm = (lane >> 3) & 1;
    const int selk = (lane >> 4) & 1;
    const u32 laneoff = (u32)(((selm * 8 + r8) * LDR + selk * 4) * 4);
    const u32 ahibase = smem_u32(RhiS) + laneoff;
    const u32 alobase = smem_u32(RloS) + laneoff;

    float acc[4][2][4];
#pragma unroll
    for (int mt = 0; mt < 4; mt++)
#pragma unroll
        for (int nt = 0; nt < 2; nt++)
#pragma unroll
            for (int q = 0; q < 4; q++) acc[mt][nt][q] = 0.0f;

    const float* __restrict__ xb = X + n0 + g;
    float raw[2][8];

#define LOADK(BUF, KS)                                                         \
    do {                                                                       \
        const size_t o  = (size_t)((KS)*16 + 2 * t) * NCOLS;                   \
        const size_t o8 = o + (size_t)8 * NCOLS;                               \
        raw[BUF][0] = xb[o];      raw[BUF][1] = xb[o + NCOLS];                 \
        raw[BUF][2] = xb[o8];     raw[BUF][3] = xb[o8 + NCOLS];                \
        raw[BUF][4] = xb[o + 8];  raw[BUF][5] = xb[o + NCOLS + 8];             \
        raw[BUF][6] = xb[o8 + 8]; raw[BUF][7] = xb[o8 + NCOLS + 8];            \
    } while (0)

    LOADK(0, 0);
    LOADK(1, 1);

#pragma unroll
    for (int ks = 0; ks < 4; ks++) {
        const int cur = ks & 1;

        u32 bhi[2][2], blo[2][2];
#pragma unroll
        for (int nt = 0; nt < 2; nt++) {
#pragma unroll
            for (int h2 = 0; h2 < 2; h2++) {
                const float x0 = raw[cur][nt * 4 + h2 * 2];
                const float x1 = raw[cur][nt * 4 + h2 * 2 + 1];
                u32 hh; CVT_PACK(hh, x1, x0);
                const float h0 = __uint_as_float(hh << 16);
                const float h1 = __uint_as_float(hh & 0xFFFF0000u);
                u32 ll; CVT_PACK(ll, x1 - h1, x0 - h0);
                bhi[nt][h2] = hh;
                blo[nt][h2] = ll;
            }
        }

        if (ks + 2 < 4) LOADK(cur, ks + 2);

#pragma unroll
        for (int mt = 0; mt < 4; mt++) {
            const u32 off = (u32)(mt * 16 * LDR * 4 + ks * 32);
            u32 ah0, ah1, ah2, ah3, al0, al1, al2, al3;
            LDMX4(ah0, ah1, ah2, ah3, ahibase + off);
            LDMX4(al0, al1, al2, al3, alobase + off);
#pragma unroll
            for (int nt = 0; nt < 2; nt++) {
                MMA_BF16(acc[mt][nt], ah0, ah1, ah2, ah3, bhi[nt][0], bhi[nt][1]);
                MMA_BF16(acc[mt][nt], ah0, ah1, ah2, ah3, blo[nt][0], blo[nt][1]);
                MMA_BF16(acc[mt][nt], al0, al1, al2, al3, bhi[nt][0], bhi[nt][1]);
            }
        }
    }
#undef LOADK

#pragma unroll
    for (int mt = 0; mt < 4; mt++) {
        const int r0 = mt * 16 + g;
#pragma unroll
        for (int nt = 0; nt < 2; nt++) {
            const long col = n0 + 8 * nt + 2 * t;
            *reinterpret_cast<float2*>(Y + (size_t)r0 * NCOLS + col) =
                make_float2(acc[mt][nt][0], acc[mt][nt][1]);
            *reinterpret_cast<float2*>(Y + (size_t)(r0 + 8) * NCOLS + col) =
                make_float2(acc[mt][nt][2], acc[mt][nt][3]);
        }
    }
}

// ---------------------------------------------------------------------------
// Inputs (metadata order): X (64*300000 f32), angles (2016 f32), mus (64 f32).
// ---------------------------------------------------------------------------
extern "C" void kernel_launch(void* const* d_in, const int* in_sizes, int n_in,
                              void* d_out, int out_size) {
    const float* X      = (const float*)d_in[0];
    const float* angles = (const float*)d_in[1];
    const float* mus    = (const float*)d_in[2];
    float* Y            = (float*)d_out;

    const int build_smem = (NSEG * NPTS * NPTS + NPTS * NPTS) * sizeof(float); // 80 KB
    cudaFuncSetAttribute(build_all_kernel,
                         cudaFuncAttributeMaxDynamicSharedMemorySize, build_smem);

    build_all_kernel<<<1, 256, build_smem>>>(angles, mus);

    const int blocks = (NCOLS + 127) / 128;   // 2344
    gemm_hmma_kernel<<<blocks, 256>>>(X, Y);
}

// round 14
// speedup vs baseline: 1.0638x; 1.0638x over previous
#include <cuda_runtime.h>
#include <cuda_bf16.h>
#include <cstdint>

#define NPTS   64
#define NANGS  2016
#define NCOLS  300000
#define LSEG   (NANGS / 2)   // 1008
#define NBLK   2

typedef unsigned int u32;

__device__ float g_M[2 * NPTS * NPTS];   // segment matrices M0, M1
__device__ float g_R[NPTS * NPTS];       // final R

// Sense-reversing 2-block barrier (g_cnt returns to 0; replay-safe).
__device__ int      g_cnt = 0;
__device__ unsigned g_gen = 0;

__device__ __forceinline__ void grid_barrier2() {
    __threadfence();
    __syncthreads();
    if (threadIdx.x == 0) {
        unsigned my = *(volatile unsigned*)&g_gen;
        if (atomicAdd(&g_cnt, 1) == NBLK - 1) {
            g_cnt = 0;
            __threadfence();
            *(volatile unsigned*)&g_gen = my + 1;
        } else {
            while (*(volatile unsigned*)&g_gen == my) { }
        }
        __threadfence();
    }
    __syncthreads();
}

__device__ __forceinline__ u32 smem_u32(const void* p) {
    u32 a;
    asm("{ .reg .u64 t; cvta.to.shared.u64 t, %1; cvt.u32.u64 %0, t; }"
        : "=r"(a) : "l"(p));
    return a;
}

// ---------------------------------------------------------------------------
// Fully-unrolled rotation chain for segment SEG: all (t,b) indices are
// compile-time constants, so the column lives entirely in registers.
// Critical path: one FFMA (4 cyc) per rotation on the carried Rc[t].
// ---------------------------------------------------------------------------
template <int SEG>
__device__ __forceinline__ void apply_chain(float (&Rc)[NPTS], const float2* cs) {
    int i = 0;
#pragma unroll
    for (int t = 0; t < NPTS - 1; t++) {
#pragma unroll
        for (int b = t + 1; b < NPTS; b++, i++) {
            if (i >= SEG * LSEG && i < (SEG + 1) * LSEG) {
                const float2 p  = cs[i - SEG * LSEG];
                const float  rb = Rc[b];
                const float  rt = Rc[t];
                Rc[b] = fmaf(p.y, rt, p.x * rb);
                Rc[t] = fmaf(p.x, rt, -(p.y * rb));
            }
        }
    }
}

// ---------------------------------------------------------------------------
// Single-launch build: 2 blocks x 256 threads.
//   Phase A: block s builds M_s = G_{(s+1)*1008-1}...G_{s*1008} (threads 0-63,
//            column per thread, registers).
//   Phase B (after 2-block barrier): block h computes 32-col half of
//            R = diag(mus) * (M1 @ M0).
// ---------------------------------------------------------------------------
__global__ void __launch_bounds__(256, 1)
build_all_kernel(const float* __restrict__ angles, const float* __restrict__ mus) {
    __shared__ float2 cs[LSEG];          // 8 KB
    __shared__ float  As[NPTS * NPTS];   // 16 KB (M1, column-major)
    __shared__ float  Bs[NPTS * 32];     // 8 KB  (M0 column half)

    const int tid = threadIdx.x;
    const int blk = blockIdx.x;          // 0 or 1

    // cos/sin table for this block's segment
    const int base = blk * LSEG;
    for (int i = tid; i < LSEG; i += 256) {
        float sv, cv;
        __sincosf(angles[base + i], &sv, &cv);
        cs[i] = make_float2(cv, sv);
    }
    __syncthreads();

    // ---- Phase A: register-resident chain (threads 0-63; thread j = column j)
    if (tid < NPTS) {
        const int j = tid;
        float Rc[NPTS];
#pragma unroll
        for (int r = 0; r < NPTS; r++) Rc[r] = (r == j) ? 1.0f : 0.0f;

        if (blk == 0) apply_chain<0>(Rc, cs);
        else          apply_chain<1>(Rc, cs);

        float* M = g_M + blk * (NPTS * NPTS);
#pragma unroll
        for (int r = 0; r < NPTS; r++) M[r * NPTS + j] = Rc[r];
    }

    grid_barrier2();

    // ---- Phase B: R = diag(mus) * (M1 @ M0); block h owns columns [32h,32h+32)
    const float* A = g_M + (NPTS * NPTS);        // M1
    const float* B = g_M + blk * 32;             // M0, column offset

    for (int idx = tid; idx < NPTS * NPTS; idx += 256) {
        const int k = idx >> 6, r = idx & 63;
        As[k * NPTS + r] = A[r * NPTS + k];      // column-major stage
    }
    for (int idx = tid; idx < NPTS * 32; idx += 256) {
        const int k = idx >> 5, jl = idx & 31;
        Bs[idx] = B[k * NPTS + jl];
    }
    __syncthreads();

    const int jl = tid & 31;
    const int rq = tid >> 5;

    float acc[8];
#pragma unroll
    for (int i = 0; i < 8; i++) acc[i] = 0.0f;

#pragma unroll 8
    for (int k = 0; k < NPTS; k++) {
        const float  b  = Bs[k * 32 + jl];
        const float4 a0 = *reinterpret_cast<const float4*>(&As[k * NPTS + rq * 8]);
        const float4 a1 = *reinterpret_cast<const float4*>(&As[k * NPTS + rq * 8 + 4]);
        acc[0] = fmaf(a0.x, b, acc[0]);
        acc[1] = fmaf(a0.y, b, acc[1]);
        acc[2] = fmaf(a0.z, b, acc[2]);
        acc[3] = fmaf(a0.w, b, acc[3]);
        acc[4] = fmaf(a1.x, b, acc[4]);
        acc[5] = fmaf(a1.y, b, acc[5]);
        acc[6] = fmaf(a1.z, b, acc[6]);
        acc[7] = fmaf(a1.w, b, acc[7]);
    }

#pragma unroll
    for (int i = 0; i < 8; i++) {
        const int r = rq * 8 + i;
        g_R[r * NPTS + blk * 32 + jl] = mus[r] * acc[i];
    }
}

// ---------------------------------------------------------------------------
// GEMM: Y = R @ X via bf16 split-precision HMMA (3-term), proven R5 form:
//   Y ~= Rhi@Xhi + Rhi@Xlo + Rlo@Xhi   (fp32 accumulate)
// Warp tile 64x16, ldmatrix.x4 A-frags, 2-deep X prefetch, 3 blocks/SM.
// ---------------------------------------------------------------------------
#define LDR 36

#define CVT_PACK(d, x1, x0) \
    asm("cvt.rn.bf16x2.f32 %0, %1, %2;" : "=r"(d) : "f"(x1), "f"(x0))

#define LDMX4(R0, R1, R2, R3, ADDR)                                            \
    asm volatile("ldmatrix.sync.aligned.m8n8.x4.shared.b16 {%0,%1,%2,%3}, [%4];" \
                 : "=r"(R0), "=r"(R1), "=r"(R2), "=r"(R3) : "r"(ADDR))

#define MMA_BF16(ACC, A0, A1, A2, A3, B0, B1)                                  \
    asm volatile(                                                              \
        "mma.sync.aligned.m16n8k16.row.col.f32.bf16.bf16.f32 "                 \
        "{%0,%1,%2,%3},{%4,%5,%6,%7},{%8,%9},{%0,%1,%2,%3};"                   \
        : "+f"(ACC[0]), "+f"(ACC[1]), "+f"(ACC[2]), "+f"(ACC[3])               \
        : "r"(A0), "r"(A1), "r"(A2), "r"(A3), "r"(B0), "r"(B1))

__global__ void __launch_bounds__(256, 3)
gemm_hmma_kernel(const float* __restrict__ X, float* __restrict__ Y) {
    __shared__ u32 RhiS[NPTS * LDR];
    __shared__ u32 RloS[NPTS * LDR];

    for (int idx = threadIdx.x; idx < NPTS * 32; idx += 256) {
        const int row = idx >> 5, kp = idx & 31;
        const float x0 = g_R[row * NPTS + 2 * kp];
        const float x1 = g_R[row * NPTS + 2 * kp + 1];
        u32 hh; CVT_PACK(hh, x1, x0);
        const float h0 = __uint_as_float(hh << 16);
        const float h1 = __uint_as_float(hh & 0xFFFF0000u);
        u32 ll; CVT_PACK(ll, x1 - h1, x0 - h0);
        RhiS[row * LDR + kp] = hh;
        RloS[row * LDR + kp] = ll;
    }
    __syncthreads();

    const int warp = threadIdx.x >> 5;
    const int lane = threadIdx.x & 31;
    const int g = lane >> 2;
    const int t = lane & 3;

    const long n0 = (long)blockIdx.x * 128 + warp * 16;
    if (n0 + 16 > NCOLS) return;

    const int r8   = lane & 7;
    const int selm = (lane >> 3) & 1;
    const int selk = (lane >> 4) & 1;
    const u32 laneoff = (u32)(((selm * 8 + r8) * LDR + selk * 4) * 4);
    const u32 ahibase = smem_u32(RhiS) + laneoff;
    const u32 alobase = smem_u32(RloS) + laneoff;

    float acc[4][2][4];
#pragma unroll
    for (int mt = 0; mt < 4; mt++)
#pragma unroll
        for (int nt = 0; nt < 2; nt++)
#pragma unroll
            for (int q = 0; q < 4; q++) acc[mt][nt][q] = 0.0f;

    const float* __restrict__ xb = X + n0 + g;
    float raw[2][8];

#define LOADK(BUF, KS)                                                         \
    do {                                                                       \
        const size_t o  = (size_t)((KS)*16 + 2 * t) * NCOLS;                   \
        const size_t o8 = o + (size_t)8 * NCOLS;                               \
        raw[BUF][0] = xb[o];      raw[BUF][1] = xb[o + NCOLS];                 \
        raw[BUF][2] = xb[o8];     raw[BUF][3] = xb[o8 + NCOLS];                \
        raw[BUF][4] = xb[o + 8];  raw[BUF][5] = xb[o + NCOLS + 8];             \
        raw[BUF][6] = xb[o8 + 8]; raw[BUF][7] = xb[o8 + NCOLS + 8];            \
    } while (0)

    LOADK(0, 0);
    LOADK(1, 1);

#pragma unroll
    for (int ks = 0; ks < 4; ks++) {
        const int cur = ks & 1;

        u32 bhi[2][2], blo[2][2];
#pragma unroll
        for (int nt = 0; nt < 2; nt++) {
#pragma unroll
            for (int h2 = 0; h2 < 2; h2++) {
                const float x0 = raw[cur][nt * 4 + h2 * 2];
                const float x1 = raw[cur][nt * 4 + h2 * 2 + 1];
                u32 hh; CVT_PACK(hh, x1, x0);
                const float h0 = __uint_as_float(hh << 16);
                const float h1 = __uint_as_float(hh & 0xFFFF0000u);
                u32 ll; CVT_PACK(ll, x1 - h1, x0 - h0);
                bhi[nt][h2] = hh;
                blo[nt][h2] = ll;
            }
        }

        if (ks + 2 < 4) LOADK(cur, ks + 2);

#pragma unroll
        for (int mt = 0; mt < 4; mt++) {
            const u32 off = (u32)(mt * 16 * LDR * 4 + ks * 32);
            u32 ah0, ah1, ah2, ah3, al0, al1, al2, al3;
            LDMX4(ah0, ah1, ah2, ah3, ahibase + off);
            LDMX4(al0, al1, al2, al3, alobase + off);
#pragma unroll
            for (int nt = 0; nt < 2; nt++) {
                MMA_BF16(acc[mt][nt], ah0, ah1, ah2, ah3, bhi[nt][0], bhi[nt][1]);
                MMA_BF16(acc[mt][nt], ah0, ah1, ah2, ah3, blo[nt][0], blo[nt][1]);
                MMA_BF16(acc[mt][nt], al0, al1, al2, al3, bhi[nt][0], bhi[nt][1]);
            }
        }
    }
#undef LOADK

#pragma unroll
    for (int mt = 0; mt < 4; mt++) {
        const int r0 = mt * 16 + g;
#pragma unroll
        for (int nt = 0; nt < 2; nt++) {
            const long col = n0 + 8 * nt + 2 * t;
            *reinterpret_cast<float2*>(Y + (size_t)r0 * NCOLS + col) =
                make_float2(acc[mt][nt][0], acc[mt][nt][1]);
            *reinterpret_cast<float2*>(Y + (size_t)(r0 + 8) * NCOLS + col) =
                make_float2(acc[mt][nt][2], acc[mt][nt][3]);
        }
    }
}

// ---------------------------------------------------------------------------
// Inputs (metadata order): X (64*300000 f32), angles (2016 f32), mus (64 f32).
// ---------------------------------------------------------------------------
extern "C" void kernel_launch(void* const* d_in, const int* in_sizes, int n_in,
                              void* d_out, int out_size) {
    const float* X      = (const float*)d_in[0];
    const float* angles = (const float*)d_in[1];
    const float* mus    = (const float*)d_in[2];
    float* Y            = (float*)d_out;

    build_all_kernel<<<NBLK, 256>>>(angles, mus);   // ONE build launch

    const int blocks = (NCOLS + 127) / 128;         // 2344
    gemm_hmma_kernel<<<blocks, 256>>>(X, Y);
}

// round 15
// speedup vs baseline: 1.2247x; 1.1512x over previous
#include <cuda_runtime.h>
#include <cuda_bf16.h>
#include <cstdint>

#define NPTS   64
#define NANGS  2016
#define NCOLS  300000
#define LSEG   (NANGS / 2)     // 1008
#define SROWS  66              // 64 state rows + 2 pad rows (preload overrun)

typedef unsigned int u32;

__device__ float g_R[NPTS * NPTS];   // final R (only cross-kernel buffer)

__device__ __forceinline__ u32 smem_u32(const void* p) {
    u32 a;
    asm("{ .reg .u64 t; cvta.to.shared.u64 t, %1; cvt.u32.u64 %0, t; }"
        : "=r"(a) : "l"(p));
    return a;
}

// ---------------------------------------------------------------------------
// Single-launch build: ONE block, 512 threads, ~50 KB dynamic smem.
//  Phase 1 (threads 0-127): 2 segments x 64 columns. Thread (s,j) applies
//    rotations [s*1008,(s+1)*1008) to column j of identity. Inner loop is
//    2-wide software-pipelined: rb/(c,s) for rotations b+2,b+3 are LOADED
//    BEFORE the stores of rotation b, so the LDS latency never sits on the
//    critical path — the chain is just the rt FFMA (~5 cyc/rotation).
//  Phase 2 (all 512 threads): R = diag(mus) * (M1 @ M0) straight from smem.
// Smem layout (floats): cs table [2*(NANGS+8)] then S0[66*64], S1[66*64].
// ---------------------------------------------------------------------------
extern __shared__ float sm_b[];

__global__ void __launch_bounds__(512, 1)
build_all_kernel(const float* __restrict__ angles, const float* __restrict__ mus) {
    float2* cs = reinterpret_cast<float2*>(sm_b);          // NANGS+8 entries
    float*  S0 = sm_b + 2 * (NANGS + 8);                   // 66*64
    float*  S1 = S0 + SROWS * NPTS;

    const int tid = threadIdx.x;

    // cos/sin table (+ zero pad) and identity-init of both states (+ pad rows)
    for (int i = tid; i < NANGS + 8; i += 512) {
        if (i < NANGS) {
            float sv, cv;
            __sincosf(angles[i], &sv, &cv);
            cs[i] = make_float2(cv, sv);
        } else {
            cs[i] = make_float2(1.0f, 0.0f);
        }
    }
    for (int idx = tid; idx < SROWS * NPTS; idx += 512) {
        const int r = idx >> 6, c = idx & 63;
        const float v = (r == c) ? 1.0f : 0.0f;
        S0[idx] = v;
        S1[idx] = v;
    }
    __syncthreads();

    // ---- Phase 1: pipelined rotation chains (threads 0-127) ----
    if (tid < 2 * NPTS) {
        const int s  = tid >> 6;          // segment 0/1
        const int j  = tid & 63;          // column
        float* Sl    = (s == 0) ? S0 : S1;
        const int i0 = s * LSEG;
        const int i1 = i0 + LSEG;

#pragma unroll 1
        for (int t = 0; t < NPTS - 1; t++) {
            const int gs   = t * (2 * NPTS - 1 - t) / 2;  // chain idx where group t starts
            const int glen = NPTS - 1 - t;
            if (gs >= i1) break;
            if (gs + glen <= i0) continue;
            int lo = i0 - gs; if (lo < 0) lo = 0;
            int hi = i1 - gs; if (hi > glen) hi = glen;
            const int bstart = t + 1 + lo;
            const int bend   = t + 1 + hi;
            const int cbase  = gs - (t + 1);              // chain idx of row b is cbase + b

            float rt = Sl[t * NPTS + j];

            // preload 2-deep (pad rows / pad cs absorb overruns)
            float  rbA = Sl[bstart * NPTS + j];
            float  rbB = Sl[(bstart + 1) * NPTS + j];
            float2 pA  = cs[cbase + bstart];
            float2 pB  = cs[cbase + bstart + 1];

            int bb = bstart;
#pragma unroll 1
            for (; bb + 2 <= bend; bb += 2) {
                // prefetch rotation bb+2, bb+3 BEFORE this iteration's stores
                const float  rb2 = Sl[(bb + 2) * NPTS + j];
                const float  rb3 = Sl[(bb + 3) * NPTS + j];
                const float2 p2  = cs[cbase + bb + 2];
                const float2 p3  = cs[cbase + bb + 3];

                Sl[bb * NPTS + j] = fmaf(pA.y, rt, pA.x * rbA);
                rt = fmaf(pA.x, rt, -(pA.y * rbA));
                Sl[(bb + 1) * NPTS + j] = fmaf(pB.y, rt, pB.x * rbB);
                rt = fmaf(pB.x, rt, -(pB.y * rbB));

                rbA = rb2; rbB = rb3; pA = p2; pB = p3;
            }
            if (bb < bend) {   // odd tail
                Sl[bb * NPTS + j] = fmaf(pA.y, rt, pA.x * rbA);
                rt = fmaf(pA.x, rt, -(pA.y * rbA));
            }
            Sl[t * NPTS + j] = rt;
        }
    }
    __syncthreads();

    // ---- Phase 2: R = diag(mus) * (S1 @ S0), 512 threads ----
    // thread -> (row r, col-group cg of 8): per k: 1 broadcast LDS (A) +
    // 2x LDS.128 (B) + 8 FMA.
    {
        const int r  = tid >> 3;          // 0..63
        const int cg = (tid & 7) * 8;     // 0,8,...,56

        float acc[8];
#pragma unroll
        for (int i = 0; i < 8; i++) acc[i] = 0.0f;

#pragma unroll 4
        for (int k = 0; k < NPTS; k++) {
            const float  a  = S1[r * NPTS + k];
            const float4 b0 = *reinterpret_cast<const float4*>(&S0[k * NPTS + cg]);
            const float4 b1 = *reinterpret_cast<const float4*>(&S0[k * NPTS + cg + 4]);
            acc[0] = fmaf(a, b0.x, acc[0]);
            acc[1] = fmaf(a, b0.y, acc[1]);
            acc[2] = fmaf(a, b0.z, acc[2]);
            acc[3] = fmaf(a, b0.w, acc[3]);
            acc[4] = fmaf(a, b1.x, acc[4]);
            acc[5] = fmaf(a, b1.y, acc[5]);
            acc[6] = fmaf(a, b1.z, acc[6]);
            acc[7] = fmaf(a, b1.w, acc[7]);
        }

        const float m = mus[r];
        float4 o0 = make_float4(m * acc[0], m * acc[1], m * acc[2], m * acc[3]);
        float4 o1 = make_float4(m * acc[4], m * acc[5], m * acc[6], m * acc[7]);
        *reinterpret_cast<float4*>(&g_R[r * NPTS + cg])     = o0;
        *reinterpret_cast<float4*>(&g_R[r * NPTS + cg + 4]) = o1;
    }
}

// ---------------------------------------------------------------------------
// GEMM: Y = R @ X via bf16 split-precision HMMA (3-term), proven R5 form:
//   Y ~= Rhi@Xhi + Rhi@Xlo + Rlo@Xhi   (fp32 accumulate)
// Warp tile 64x16, ldmatrix.x4 A-frags, 2-deep X prefetch, 3 blocks/SM.
// ---------------------------------------------------------------------------
#define LDR 36

#define CVT_PACK(d, x1, x0) \
    asm("cvt.rn.bf16x2.f32 %0, %1, %2;" : "=r"(d) : "f"(x1), "f"(x0))

#define LDMX4(R0, R1, R2, R3, ADDR)                                            \
    asm volatile("ldmatrix.sync.aligned.m8n8.x4.shared.b16 {%0,%1,%2,%3}, [%4];" \
                 : "=r"(R0), "=r"(R1), "=r"(R2), "=r"(R3) : "r"(ADDR))

#define MMA_BF16(ACC, A0, A1, A2, A3, B0, B1)                                  \
    asm volatile(                                                              \
        "mma.sync.aligned.m16n8k16.row.col.f32.bf16.bf16.f32 "                 \
        "{%0,%1,%2,%3},{%4,%5,%6,%7},{%8,%9},{%0,%1,%2,%3};"                   \
        : "+f"(ACC[0]), "+f"(ACC[1]), "+f"(ACC[2]), "+f"(ACC[3])               \
        : "r"(A0), "r"(A1), "r"(A2), "r"(A3), "r"(B0), "r"(B1))

__global__ void __launch_bounds__(256, 3)
gemm_hmma_kernel(const float* __restrict__ X, float* __restrict__ Y) {
    __shared__ u32 RhiS[NPTS * LDR];
    __shared__ u32 RloS[NPTS * LDR];

    for (int idx = threadIdx.x; idx < NPTS * 32; idx += 256) {
        const int row = idx >> 5, kp = idx & 31;
        const float x0 = g_R[row * NPTS + 2 * kp];
        const float x1 = g_R[row * NPTS + 2 * kp + 1];
        u32 hh; CVT_PACK(hh, x1, x0);
        const float h0 = __uint_as_float(hh << 16);
        const float h1 = __uint_as_float(hh & 0xFFFF0000u);
        u32 ll; CVT_PACK(ll, x1 - h1, x0 - h0);
        RhiS[row * LDR + kp] = hh;
        RloS[row * LDR + kp] = ll;
    }
    __syncthreads();

    const int warp = threadIdx.x >> 5;
    const int lane = threadIdx.x & 31;
    const int g = lane >> 2;
    const int t = lane & 3;

    const long n0 = (long)blockIdx.x * 128 + warp * 16;
    if (n0 + 16 > NCOLS) return;

    const int r8   = lane & 7;
    const int selm = (lane >> 3) & 1;
    const int selk = (lane >> 4) & 1;
    const u32 laneoff = (u32)(((selm * 8 + r8) * LDR + selk * 4) * 4);
    const u32 ahibase = smem_u32(RhiS) + laneoff;
    const u32 alobase = smem_u32(RloS) + laneoff;

    float acc[4][2][4];
#pragma unroll
    for (int mt = 0; mt < 4; mt++)
#pragma unroll
        for (int nt = 0; nt < 2; nt++)
#pragma unroll
            for (int q = 0; q < 4; q++) acc[mt][nt][q] = 0.0f;

    const float* __restrict__ xb = X + n0 + g;
    float raw[2][8];

#define LOADK(BUF, KS)                                                         \
    do {                                                                       \
        const size_t o  = (size_t)((KS)*16 + 2 * t) * NCOLS;                   \
        const size_t o8 = o + (size_t)8 * NCOLS;                               \
        raw[BUF][0] = xb[o];      raw[BUF][1] = xb[o + NCOLS];                 \
        raw[BUF][2] = xb[o8];     raw[BUF][3] = xb[o8 + NCOLS];                \
        raw[BUF][4] = xb[o + 8];  raw[BUF][5] = xb[o + NCOLS + 8];             \
        raw[BUF][6] = xb[o8 + 8]; raw[BUF][7] = xb[o8 + NCOLS + 8];            \
    } while (0)

    LOADK(0, 0);
    LOADK(1, 1);

#pragma unroll
    for (int ks = 0; ks < 4; ks++) {
        const int cur = ks & 1;

        u32 bhi[2][2], blo[2][2];
#pragma unroll
        for (int nt = 0; nt < 2; nt++) {
#pragma unroll
            for (int h2 = 0; h2 < 2; h2++) {
                const float x0 = raw[cur][nt * 4 + h2 * 2];
                const float x1 = raw[cur][nt * 4 + h2 * 2 + 1];
                u32 hh; CVT_PACK(hh, x1, x0);
                const float h0 = __uint_as_float(hh << 16);
                const float h1 = __uint_as_float(hh & 0xFFFF0000u);
                u32 ll; CVT_PACK(ll, x1 - h1, x0 - h0);
                bhi[nt][h2] = hh;
                blo[nt][h2] = ll;
            }
        }

        if (ks + 2 < 4) LOADK(cur, ks + 2);

#pragma unroll
        for (int mt = 0; mt < 4; mt++) {
            const u32 off = (u32)(mt * 16 * LDR * 4 + ks * 32);
            u32 ah0, ah1, ah2, ah3, al0, al1, al2, al3;
            LDMX4(ah0, ah1, ah2, ah3, ahibase + off);
            LDMX4(al0, al1, al2, al3, alobase + off);
#pragma unroll
            for (int nt = 0; nt < 2; nt++) {
                MMA_BF16(acc[mt][nt], ah0, ah1, ah2, ah3, bhi[nt][0], bhi[nt][1]);
                MMA_BF16(acc[mt][nt], ah0, ah1, ah2, ah3, blo[nt][0], blo[nt][1]);
                MMA_BF16(acc[mt][nt], al0, al1, al2, al3, bhi[nt][0], bhi[nt][1]);
            }
        }
    }
#undef LOADK

#pragma unroll
    for (int mt = 0; mt < 4; mt++) {
        const int r0 = mt * 16 + g;
#pragma unroll
        for (int nt = 0; nt < 2; nt++) {
            const long col = n0 + 8 * nt + 2 * t;
            *reinterpret_cast<float2*>(Y + (size_t)r0 * NCOLS + col) =
                make_float2(acc[mt][nt][0], acc[mt][nt][1]);
            *reinterpret_cast<float2*>(Y + (size_t)(r0 + 8) * NCOLS + col) =
                make_float2(acc[mt][nt][2], acc[mt][nt][3]);
        }
    }
}

// ---------------------------------------------------------------------------
// Inputs (metadata order): X (64*300000 f32), angles (2016 f32), mus (64 f32).
// ---------------------------------------------------------------------------
extern "C" void kernel_launch(void* const* d_in, const int* in_sizes, int n_in,
                              void* d_out, int out_size) {
    const float* X      = (const float*)d_in[0];
    const float* angles = (const float*)d_in[1];
    const float* mus    = (const float*)d_in[2];
    float* Y            = (float*)d_out;

    const int build_smem = (2 * (NANGS + 8) + 2 * SROWS * NPTS) * (int)sizeof(float);
    cudaFuncSetAttribute(build_all_kernel,
                         cudaFuncAttributeMaxDynamicSharedMemorySize, build_smem);

    build_all_kernel<<<1, 512, build_smem>>>(angles, mus);   // ONE build launch

    const int blocks = (NCOLS + 127) / 128;                  // 2344
    gemm_hmma_kernel<<<blocks, 256>>>(X, Y);
}